// round 8
// baseline (speedup 1.0000x reference)
#include <cuda_runtime.h>

#define B_ROWS 16384
#define IN_DIM 2048
#define E_NUM 16
#define KMAX 8

#define TEMP_F 0.7f
#define P_MIN_F 0.92f
#define CLOSE_F 0.82f   // P_MIN - CLOSE_DELTA

#define SC_OFF (B_ROWS * KMAX)          // 131072
#define MK_OFF (2 * B_ROWS * KMAX)      // 262144
#define KV_OFF (3 * B_ROWS * KMAX)      // 393216

#define NBODY 16        // K bodies of 128 floats
#define WCHUNK (E_NUM * 128)            // floats per W1 body chunk (2048)

// ---- cp.async helpers ------------------------------------------------------
__device__ __forceinline__ void cp_async16(unsigned saddr, const void* gaddr) {
    asm volatile("cp.async.cg.shared.global [%0], [%1], 16;" :: "r"(saddr), "l"(gaddr));
}
__device__ __forceinline__ void cp_commit() {
    asm volatile("cp.async.commit_group;");
}
template <int N>
__device__ __forceinline__ void cp_wait() {
    asm volatile("cp.async.wait_group %0;" :: "n"(N));
}

// FMA body: W1 chunk read from shared (guaranteed hit), x in registers
#define FMA_BODY_S(v0, v1, v2, v3, wsrow)                                     \
    {                                                                         \
        const float* wp_ = (wsrow) + (lane << 2);                             \
        _Pragma("unroll")                                                     \
        for (int e = 0; e < E_NUM; e++) {                                     \
            float4 w = *reinterpret_cast<const float4*>(wp_ + e * 128);       \
            acc[e * 4 + 0] = fmaf(w.x, v0.x, acc[e * 4 + 0]);                 \
            acc[e * 4 + 0] = fmaf(w.y, v0.y, acc[e * 4 + 0]);                 \
            acc[e * 4 + 0] = fmaf(w.z, v0.z, acc[e * 4 + 0]);                 \
            acc[e * 4 + 0] = fmaf(w.w, v0.w, acc[e * 4 + 0]);                 \
            acc[e * 4 + 1] = fmaf(w.x, v1.x, acc[e * 4 + 1]);                 \
            acc[e * 4 + 1] = fmaf(w.y, v1.y, acc[e * 4 + 1]);                 \
            acc[e * 4 + 1] = fmaf(w.z, v1.z, acc[e * 4 + 1]);                 \
            acc[e * 4 + 1] = fmaf(w.w, v1.w, acc[e * 4 + 1]);                 \
            acc[e * 4 + 2] = fmaf(w.x, v2.x, acc[e * 4 + 2]);                 \
            acc[e * 4 + 2] = fmaf(w.y, v2.y, acc[e * 4 + 2]);                 \
            acc[e * 4 + 2] = fmaf(w.z, v2.z, acc[e * 4 + 2]);                 \
            acc[e * 4 + 2] = fmaf(w.w, v2.w, acc[e * 4 + 2]);                 \
            acc[e * 4 + 3] = fmaf(w.x, v3.x, acc[e * 4 + 3]);                 \
            acc[e * 4 + 3] = fmaf(w.y, v3.y, acc[e * 4 + 3]);                 \
            acc[e * 4 + 3] = fmaf(w.z, v3.z, acc[e * 4 + 3]);                 \
            acc[e * 4 + 3] = fmaf(w.w, v3.w, acc[e * 4 + 3]);                 \
        }                                                                     \
    }

__global__ __launch_bounds__(128, 5) void dyn_top_gate_kernel(
    const float* __restrict__ x,
    const float* __restrict__ W1,
    const float* __restrict__ W2,
    float* __restrict__ out)
{
    __shared__ __align__(16) float ws[2][WCHUNK];   // 16 KB double-buffered W1

    const int tid = threadIdx.x;
    const int lane = tid & 31;
    const int wid = tid >> 5;
    const int row0 = (blockIdx.x * 4 + wid) * 4;

    const float* xr = x + (size_t)row0 * IN_DIM;

    // ---- stage W1 body 0 ---------------------------------------------------
    {
        unsigned sbase = (unsigned)__cvta_generic_to_shared(&ws[0][0]);
#pragma unroll
        for (int i = 0; i < 4; i++) {
            int idx = tid + i * 128;                       // 0..511
            int e = idx >> 5, k4 = idx & 31;
            cp_async16(sbase + idx * 16, W1 + e * IN_DIM + k4 * 4);
        }
        cp_commit();
    }

    float acc[64];
#pragma unroll
    for (int i = 0; i < 64; i++) acc[i] = 0.f;

    int off = lane * 4;
    float4 a0 = __ldcs(reinterpret_cast<const float4*>(xr + off));
    float4 a1 = __ldcs(reinterpret_cast<const float4*>(xr + IN_DIM + off));
    float4 a2 = __ldcs(reinterpret_cast<const float4*>(xr + 2 * IN_DIM + off));
    float4 a3 = __ldcs(reinterpret_cast<const float4*>(xr + 3 * IN_DIM + off));
    float4 b0, b1, b2, b3;

#pragma unroll 1
    for (int it = 0; it < NBODY; it += 2) {
        // ===== body it: buffer a, ws[it&1] =====
        __syncthreads();                        // all done reading ws[(it+1)&1]
        {   // stage W1 body it+1 (always exists: it <= 14)
            unsigned sbase = (unsigned)__cvta_generic_to_shared(&ws[(it + 1) & 1][0]);
            const float* wsrc = W1 + (it + 1) * 128;
#pragma unroll
            for (int i = 0; i < 4; i++) {
                int idx = tid + i * 128;
                int e = idx >> 5, k4 = idx & 31;
                cp_async16(sbase + idx * 16, wsrc + e * IN_DIM + k4 * 4);
            }
            cp_commit();
        }
        const int offb = off + 128;
        b0 = __ldcs(reinterpret_cast<const float4*>(xr + offb));
        b1 = __ldcs(reinterpret_cast<const float4*>(xr + IN_DIM + offb));
        b2 = __ldcs(reinterpret_cast<const float4*>(xr + 2 * IN_DIM + offb));
        b3 = __ldcs(reinterpret_cast<const float4*>(xr + 3 * IN_DIM + offb));
        cp_wait<1>();                           // body it's chunk complete
        __syncthreads();
        FMA_BODY_S(a0, a1, a2, a3, &ws[it & 1][0]);

        // ===== body it+1: buffer b, ws[(it+1)&1] =====
        __syncthreads();                        // all done reading ws[it&1]
        if (it + 2 < NBODY) {
            unsigned sbase = (unsigned)__cvta_generic_to_shared(&ws[it & 1][0]);
            const float* wsrc = W1 + (it + 2) * 128;
#pragma unroll
            for (int i = 0; i < 4; i++) {
                int idx = tid + i * 128;
                int e = idx >> 5, k4 = idx & 31;
                cp_async16(sbase + idx * 16, wsrc + e * IN_DIM + k4 * 4);
            }
            cp_commit();
        }
        const int offa = off + 256;
        if (offa < IN_DIM) {                    // warp-uniform; false only last trip
            a0 = __ldcs(reinterpret_cast<const float4*>(xr + offa));
            a1 = __ldcs(reinterpret_cast<const float4*>(xr + IN_DIM + offa));
            a2 = __ldcs(reinterpret_cast<const float4*>(xr + 2 * IN_DIM + offa));
            a3 = __ldcs(reinterpret_cast<const float4*>(xr + 3 * IN_DIM + offa));
        }
        if (it + 2 < NBODY) cp_wait<1>(); else cp_wait<0>();
        __syncthreads();
        FMA_BODY_S(b0, b1, b2, b3, &ws[(it + 1) & 1][0]);

        off = offa;
    }

    // ----- butterfly distribute-reduce: 64 slots -> 2 fully-reduced / lane --
    // slot s = (r1 e3 e2 e1 e0 r0); lane l=f+16g ends holding slots {2l,2l+1}
    float vals[64];
#pragma unroll
    for (int e = 0; e < E_NUM; e++) {
#pragma unroll
        for (int r = 0; r < 4; r++)
            vals[((r & 2) << 4) | (e << 1) | (r & 1)] = acc[e * 4 + r];
    }

#pragma unroll
    for (int offx = 16, cnt = 32; offx >= 1; offx >>= 1, cnt >>= 1) {
        const bool up = (lane & offx) != 0;
#pragma unroll
        for (int i = 0; i < cnt; i++) {
            float send = up ? vals[i] : vals[i + cnt];
            float keep = up ? vals[i + cnt] : vals[i];
            float recv = __shfl_xor_sync(0xffffffffu, send, offx);
            vals[i] = keep + recv;
        }
    }

    const int g = lane >> 4;
    const int f = lane & 15;

    const float th0 = tanhf(vals[0]);
    const float th1 = tanhf(vals[1]);

    float w2f[E_NUM];
#pragma unroll
    for (int e = 0; e < E_NUM; e++) w2f[e] = __ldg(W2 + f * E_NUM + e);

#pragma unroll
    for (int rr = 0; rr < 2; rr++) {
        const int row = row0 + 2 * g + rr;
        const float tsel = rr ? th1 : th0;

        float logit = 0.f;
#pragma unroll
        for (int e = 0; e < E_NUM; e++) {
            float hv = __shfl_sync(0xffffffffu, tsel, (g << 4) | e);
            logit = fmaf(hv, w2f[e], logit);
        }
        logit = logit / TEMP_F;

        float m = logit;
#pragma unroll
        for (int s = 8; s > 0; s >>= 1)
            m = fmaxf(m, __shfl_xor_sync(0xffffffffu, m, s, 16));

        float ex = expf(logit - m);
        float sum = ex;
#pragma unroll
        for (int s = 8; s > 0; s >>= 1)
            sum += __shfl_xor_sync(0xffffffffu, sum, s, 16);
        float prob = ex / sum;

        int rank = 0;
#pragma unroll
        for (int g2 = 0; g2 < E_NUM; g2++) {
            float lv = __shfl_sync(0xffffffffu, logit, g2, 16);
            rank += (lv > logit) || (lv == logit && g2 < f);
        }

        float cum = 0.f, p1 = 0.f, p2 = 0.f, p3 = 0.f;
#pragma unroll
        for (int g2 = 0; g2 < E_NUM; g2++) {
            float pv = __shfl_sync(0xffffffffu, prob, g2, 16);
            int rv = __shfl_sync(0xffffffffu, rank, g2, 16);
            if (rv <= rank) cum += pv;
            if (rv == 0) p1 = pv;
            if (rv == 1) p2 = pv;
            if (rv == 2) p3 = pv;
        }

        int cnt2 = 0;
#pragma unroll
        for (int g2 = 0; g2 < E_NUM; g2++) {
            float cv = __shfl_sync(0xffffffffu, cum, g2, 16);
            cnt2 += (cv < P_MIN_F);
        }
        if (cnt2 > E_NUM - 1) cnt2 = E_NUM - 1;
        int kv = cnt2 + 1;

        float gap12 = p1 - p2;
        float gap23 = p2 - p3;
        if (p1 >= 0.46f && gap12 >= 0.1f) kv = 1;
        float cum1 = p1 + p2;
        if (kv > 2 && (cum1 >= CLOSE_F || p3 <= 0.12f || gap23 <= 0.03f)) kv = 2;
        kv = max(1, min(3, kv));

        if (rank < KMAX) {
            int o = row * KMAX + rank;
            out[o] = (float)f;                                   // top_indices
            out[SC_OFF + o] = (rank < kv) ? prob : 0.f;          // top_scores
            out[MK_OFF + o] = (rank < kv) ? 1.f : 0.f;           // top_mask
        }
        if (rank == 0) out[KV_OFF + row] = (float)kv;            // k_vec
    }
}

extern "C" void kernel_launch(void* const* d_in, const int* in_sizes, int n_in,
                              void* d_out, int out_size) {
    const float* x  = (const float*)d_in[0];
    const float* W1 = (const float*)d_in[1];
    const float* W2 = (const float*)d_in[2];
    float* out = (float*)d_out;

    // 4 rows per warp, 4 warps per block -> 16 rows/block
    const int blocks = B_ROWS / 16;  // 1024
    dyn_top_gate_kernel<<<blocks, 128>>>(x, W1, W2, out);
}

// round 10
// speedup vs baseline: 2.2105x; 2.2105x over previous
#include <cuda_runtime.h>

#define B_ROWS 16384
#define IN_DIM 2048
#define E_NUM 16
#define KMAX 8

#define TEMP_F 0.7f
#define P_MIN_F 0.92f
#define CLOSE_F 0.82f   // P_MIN - CLOSE_DELTA

#define SC_OFF (B_ROWS * KMAX)          // 131072
#define MK_OFF (2 * B_ROWS * KMAX)      // 262144
#define KV_OFF (3 * B_ROWS * KMAX)      // 393216

#define NBODY 16                        // K bodies of 128 floats
#define W1_FLOATS (E_NUM * IN_DIM)      // 32768 floats = 128 KB
#define W1_VEC4 (W1_FLOATS / 4)         // 8192 float4
#define THREADS 512
#define ROWS_PER_BLOCK 64               // 16 warps * 4 rows

// ---- cp.async helpers ------------------------------------------------------
__device__ __forceinline__ void cp_async16(unsigned saddr, const void* gaddr) {
    asm volatile("cp.async.cg.shared.global [%0], [%1], 16;" :: "r"(saddr), "l"(gaddr));
}
__device__ __forceinline__ void cp_commit() {
    asm volatile("cp.async.commit_group;");
}
__device__ __forceinline__ void cp_wait0() {
    asm volatile("cp.async.wait_group 0;");
}

// FMA body: W1 read from smem (guaranteed conflict-free hit), x in registers.
// wsp points at ws + body_off + lane*4 ; expert stride = IN_DIM floats.
#define FMA_BODY_S(v0, v1, v2, v3, wsp)                                       \
    {                                                                         \
        _Pragma("unroll")                                                     \
        for (int e = 0; e < E_NUM; e++) {                                     \
            float4 w = *reinterpret_cast<const float4*>((wsp) + e * IN_DIM);  \
            acc[e * 4 + 0] = fmaf(w.x, v0.x, acc[e * 4 + 0]);                 \
            acc[e * 4 + 0] = fmaf(w.y, v0.y, acc[e * 4 + 0]);                 \
            acc[e * 4 + 0] = fmaf(w.z, v0.z, acc[e * 4 + 0]);                 \
            acc[e * 4 + 0] = fmaf(w.w, v0.w, acc[e * 4 + 0]);                 \
            acc[e * 4 + 1] = fmaf(w.x, v1.x, acc[e * 4 + 1]);                 \
            acc[e * 4 + 1] = fmaf(w.y, v1.y, acc[e * 4 + 1]);                 \
            acc[e * 4 + 1] = fmaf(w.z, v1.z, acc[e * 4 + 1]);                 \
            acc[e * 4 + 1] = fmaf(w.w, v1.w, acc[e * 4 + 1]);                 \
            acc[e * 4 + 2] = fmaf(w.x, v2.x, acc[e * 4 + 2]);                 \
            acc[e * 4 + 2] = fmaf(w.y, v2.y, acc[e * 4 + 2]);                 \
            acc[e * 4 + 2] = fmaf(w.z, v2.z, acc[e * 4 + 2]);                 \
            acc[e * 4 + 2] = fmaf(w.w, v2.w, acc[e * 4 + 2]);                 \
            acc[e * 4 + 3] = fmaf(w.x, v3.x, acc[e * 4 + 3]);                 \
            acc[e * 4 + 3] = fmaf(w.y, v3.y, acc[e * 4 + 3]);                 \
            acc[e * 4 + 3] = fmaf(w.z, v3.z, acc[e * 4 + 3]);                 \
            acc[e * 4 + 3] = fmaf(w.w, v3.w, acc[e * 4 + 3]);                 \
        }                                                                     \
    }

__global__ __launch_bounds__(THREADS, 1) void dyn_top_gate_kernel(
    const float* __restrict__ x,
    const float* __restrict__ W1,
    const float* __restrict__ W2,
    float* __restrict__ out)
{
    extern __shared__ __align__(16) float ws[];     // all of W1: 128 KB

    const int tid = threadIdx.x;
    const int lane = tid & 31;
    const int wid = tid >> 5;                       // 0..15
    const int row0 = blockIdx.x * ROWS_PER_BLOCK + wid * 4;

    // ---- stage ALL of W1 into smem once (cp.async, L1-bypass) -------------
    {
        unsigned sbase = (unsigned)__cvta_generic_to_shared(ws);
        const float4* wsrc = reinterpret_cast<const float4*>(W1);
#pragma unroll
        for (int i = 0; i < W1_VEC4 / THREADS; i++) {   // 16 per thread
            int idx = tid + i * THREADS;
            cp_async16(sbase + idx * 16, wsrc + idx);
        }
        cp_commit();
    }

    float acc[64];
#pragma unroll
    for (int i = 0; i < 64; i++) acc[i] = 0.f;

    const float* xr = x + (size_t)row0 * IN_DIM;

    // first x chunk issued while W1 staging is in flight
    int off = lane * 4;
    float4 a0 = __ldcs(reinterpret_cast<const float4*>(xr + off));
    float4 a1 = __ldcs(reinterpret_cast<const float4*>(xr + IN_DIM + off));
    float4 a2 = __ldcs(reinterpret_cast<const float4*>(xr + 2 * IN_DIM + off));
    float4 a3 = __ldcs(reinterpret_cast<const float4*>(xr + 3 * IN_DIM + off));
    float4 b0, b1, b2, b3;

    cp_wait0();
    __syncthreads();                                // W1 resident; only sync

#pragma unroll 1
    for (int it = 0; it < NBODY; it += 2) {
        const int offb = off + 128;                 // always < IN_DIM here
        b0 = __ldcs(reinterpret_cast<const float4*>(xr + offb));
        b1 = __ldcs(reinterpret_cast<const float4*>(xr + IN_DIM + offb));
        b2 = __ldcs(reinterpret_cast<const float4*>(xr + 2 * IN_DIM + offb));
        b3 = __ldcs(reinterpret_cast<const float4*>(xr + 3 * IN_DIM + offb));

        FMA_BODY_S(a0, a1, a2, a3, ws + off);

        const int offa = off + 256;
        if (offa < IN_DIM) {                        // warp-uniform; last trip only
            a0 = __ldcs(reinterpret_cast<const float4*>(xr + offa));
            a1 = __ldcs(reinterpret_cast<const float4*>(xr + IN_DIM + offa));
            a2 = __ldcs(reinterpret_cast<const float4*>(xr + 2 * IN_DIM + offa));
            a3 = __ldcs(reinterpret_cast<const float4*>(xr + 3 * IN_DIM + offa));
        }

        FMA_BODY_S(b0, b1, b2, b3, ws + offb);

        off = offa;
    }

    // ----- butterfly distribute-reduce: 64 slots -> 2 fully-reduced / lane --
    // slot s = (r1 e3 e2 e1 e0 r0); lane l=f+16g ends holding slots {2l,2l+1}
    float vals[64];
#pragma unroll
    for (int e = 0; e < E_NUM; e++) {
#pragma unroll
        for (int r = 0; r < 4; r++)
            vals[((r & 2) << 4) | (e << 1) | (r & 1)] = acc[e * 4 + r];
    }

#pragma unroll
    for (int offx = 16, cnt = 32; offx >= 1; offx >>= 1, cnt >>= 1) {
        const bool up = (lane & offx) != 0;
#pragma unroll
        for (int i = 0; i < cnt; i++) {
            float send = up ? vals[i] : vals[i + cnt];
            float keep = up ? vals[i + cnt] : vals[i];
            float recv = __shfl_xor_sync(0xffffffffu, send, offx);
            vals[i] = keep + recv;
        }
    }

    const int g = lane >> 4;
    const int f = lane & 15;

    const float th0 = tanhf(vals[0]);
    const float th1 = tanhf(vals[1]);

    float w2f[E_NUM];
#pragma unroll
    for (int e = 0; e < E_NUM; e++) w2f[e] = __ldg(W2 + f * E_NUM + e);

#pragma unroll
    for (int rr = 0; rr < 2; rr++) {
        const int row = row0 + 2 * g + rr;
        const float tsel = rr ? th1 : th0;

        // gather h[e] for my row: lives at lane e + 16*g
        float logit = 0.f;
#pragma unroll
        for (int e = 0; e < E_NUM; e++) {
            float hv = __shfl_sync(0xffffffffu, tsel, (g << 4) | e);
            logit = fmaf(hv, w2f[e], logit);
        }
        logit = logit / TEMP_F;

        // softmax over the 16-lane segment
        float m = logit;
#pragma unroll
        for (int s = 8; s > 0; s >>= 1)
            m = fmaxf(m, __shfl_xor_sync(0xffffffffu, m, s, 16));

        float ex = expf(logit - m);
        float sum = ex;
#pragma unroll
        for (int s = 8; s > 0; s >>= 1)
            sum += __shfl_xor_sync(0xffffffffu, sum, s, 16);
        float prob = ex / sum;

        // stable descending rank (ties -> smaller expert index first)
        int rank = 0;
#pragma unroll
        for (int g2 = 0; g2 < E_NUM; g2++) {
            float lv = __shfl_sync(0xffffffffu, logit, g2, 16);
            rank += (lv > logit) || (lv == logit && g2 < f);
        }

        // inclusive cumulative prob at my rank; pick p1,p2,p3
        float cum = 0.f, p1 = 0.f, p2 = 0.f, p3 = 0.f;
#pragma unroll
        for (int g2 = 0; g2 < E_NUM; g2++) {
            float pv = __shfl_sync(0xffffffffu, prob, g2, 16);
            int rv = __shfl_sync(0xffffffffu, rank, g2, 16);
            if (rv <= rank) cum += pv;
            if (rv == 0) p1 = pv;
            if (rv == 1) p2 = pv;
            if (rv == 2) p3 = pv;
        }

        // idx_first = #ranks with cum < P_MIN (cum monotone in rank)
        int cnt2 = 0;
#pragma unroll
        for (int g2 = 0; g2 < E_NUM; g2++) {
            float cv = __shfl_sync(0xffffffffu, cum, g2, 16);
            cnt2 += (cv < P_MIN_F);
        }
        if (cnt2 > E_NUM - 1) cnt2 = E_NUM - 1;
        int kv = cnt2 + 1;

        float gap12 = p1 - p2;
        float gap23 = p2 - p3;
        if (p1 >= 0.46f && gap12 >= 0.1f) kv = 1;
        float cum1 = p1 + p2;
        if (kv > 2 && (cum1 >= CLOSE_F || p3 <= 0.12f || gap23 <= 0.03f)) kv = 2;
        kv = max(1, min(3, kv));

        // ----- writes -----
        if (rank < KMAX) {
            int o = row * KMAX + rank;
            out[o] = (float)f;                                   // top_indices
            out[SC_OFF + o] = (rank < kv) ? prob : 0.f;          // top_scores
            out[MK_OFF + o] = (rank < kv) ? 1.f : 0.f;           // top_mask
        }
        if (rank == 0) out[KV_OFF + row] = (float)kv;            // k_vec
    }
}

extern "C" void kernel_launch(void* const* d_in, const int* in_sizes, int n_in,
                              void* d_out, int out_size) {
    const float* x  = (const float*)d_in[0];
    const float* W1 = (const float*)d_in[1];
    const float* W2 = (const float*)d_in[2];
    float* out = (float*)d_out;

    const int smem_bytes = W1_FLOATS * 4;  // 131072
    static int attr_set = 0;
    if (!attr_set) {
        cudaFuncSetAttribute(dyn_top_gate_kernel,
                             cudaFuncAttributeMaxDynamicSharedMemorySize,
                             smem_bytes);
        attr_set = 1;
    }

    const int blocks = B_ROWS / ROWS_PER_BLOCK;   // 256
    dyn_top_gate_kernel<<<blocks, THREADS, smem_bytes>>>(x, W1, W2, out);
}